// round 14
// baseline (speedup 1.0000x reference)
#include <cuda_runtime.h>
#include <cstdint>
#include <cstddef>

// ---------------------------------------------------------------------------
// Problem dims (fixed): B=4, T=2048, C=2048, H=16, HD=128
// ---------------------------------------------------------------------------
#define B_  4
#define T_  2048
#define C_  2048
#define BT_ (B_ * T_)          // 8192
#define C3_ (3 * C_)           // 6144
#define C4_ (4 * C_)           // 8192
#define NH_ 16
#define HD_ 128

// ---------------------------------------------------------------------------
// Scratch (device globals: allocation-free rule)
// ---------------------------------------------------------------------------
__device__ float g_h[(size_t)BT_ * C_];       // LN output (tf32-rounded)
__device__ float g_qkv[(size_t)BT_ * C3_];    // Q,K (V third unused)
__device__ float g_vt[(size_t)BT_ * C_];      // V transposed: [b*h][d][t]
__device__ float g_y[(size_t)BT_ * C_];       // attention output (tf32-rounded)
__device__ float g_fc[(size_t)BT_ * C4_];     // gelu(fc) (tf32-rounded)
__device__ float g_wt_attn[(size_t)C3_ * C_];    // w_attn^T rounded
__device__ float g_wt_proj[(size_t)C_ * C_];     // w_proj^T rounded
__device__ float g_wt_fc[(size_t)C4_ * C_];      // w_fc^T rounded
__device__ float g_wt_fcproj[(size_t)C_ * C4_];  // w_fc_proj^T rounded

// ---------------------------------------------------------------------------
// Helpers
// ---------------------------------------------------------------------------
__device__ __forceinline__ uint32_t smem_u32(const void* p)
{
    return (uint32_t)__cvta_generic_to_shared(p);
}
#define CP_ASYNC16(dst, src) \
    asm volatile("cp.async.cg.shared.global [%0], [%1], 16;" \
                 :: "r"(dst), "l"(src) : "memory")
#define CP_COMMIT() asm volatile("cp.async.commit_group;" ::: "memory")
#define CP_WAIT(n)  asm volatile("cp.async.wait_group %0;" :: "n"(n) : "memory")

__device__ __forceinline__ float tf32r(float v)
{
    uint32_t u;
    asm("cvt.rna.tf32.f32 %0, %1;" : "=r"(u) : "f"(v));
    return __uint_as_float(u);
}

__device__ __forceinline__ void mma_tf32(float* c, const uint32_t* a,
                                         const uint32_t* b)
{
    asm volatile(
        "mma.sync.aligned.m16n8k8.row.col.f32.tf32.tf32.f32 "
        "{%0,%1,%2,%3}, {%4,%5,%6,%7}, {%8,%9}, {%0,%1,%2,%3};"
        : "+f"(c[0]), "+f"(c[1]), "+f"(c[2]), "+f"(c[3])
        : "r"(a[0]), "r"(a[1]), "r"(a[2]), "r"(a[3]), "r"(b[0]), "r"(b[1]));
}

// ---------------------------------------------------------------------------
// Weight transpose + tf32 rounding: in[R][Cc] -> out[Cc][R]
// ---------------------------------------------------------------------------
__global__ __launch_bounds__(256) void transpose_k(const float* __restrict__ in,
                                                   float* __restrict__ out,
                                                   int R, int Cc)
{
    __shared__ float t[32][33];
    int tx = threadIdx.x, ty = threadIdx.y;
    int bx = blockIdx.x * 32, by = blockIdx.y * 32;
    #pragma unroll
    for (int j = 0; j < 32; j += 8)
        t[ty + j][tx] = in[(size_t)(by + ty + j) * Cc + bx + tx];
    __syncthreads();
    #pragma unroll
    for (int j = 0; j < 32; j += 8)
        out[(size_t)(bx + ty + j) * R + by + tx] = tf32r(t[tx][ty + j]);
}

// ---------------------------------------------------------------------------
// LayerNorm: one block per row of 2048; output rounded to tf32 values
// ---------------------------------------------------------------------------
__global__ __launch_bounds__(256) void ln_k(const float* __restrict__ x,
                                            const float* __restrict__ g,
                                            const float* __restrict__ b,
                                            float* __restrict__ out)
{
    size_t row = blockIdx.x;
    const float4* xr = (const float4*)(x + row * (size_t)C_);
    int tid = threadIdx.x;
    float4 v0 = xr[tid];
    float4 v1 = xr[tid + 256];
    float s  = v0.x + v0.y + v0.z + v0.w + v1.x + v1.y + v1.z + v1.w;
    float s2 = v0.x*v0.x + v0.y*v0.y + v0.z*v0.z + v0.w*v0.w
             + v1.x*v1.x + v1.y*v1.y + v1.z*v1.z + v1.w*v1.w;
    #pragma unroll
    for (int o = 16; o > 0; o >>= 1) {
        s  += __shfl_xor_sync(0xffffffffu, s,  o);
        s2 += __shfl_xor_sync(0xffffffffu, s2, o);
    }
    __shared__ float ssum[8], ssq[8];
    __shared__ float mu_s, inv_s;
    int wid = tid >> 5, lane = tid & 31;
    if (lane == 0) { ssum[wid] = s; ssq[wid] = s2; }
    __syncthreads();
    if (tid == 0) {
        float S = 0.f, S2 = 0.f;
        #pragma unroll
        for (int i = 0; i < 8; ++i) { S += ssum[i]; S2 += ssq[i]; }
        float mu  = S * (1.f / (float)C_);
        float var = S2 * (1.f / (float)C_) - mu * mu;
        mu_s  = mu;
        inv_s = rsqrtf(var + 1e-5f);
    }
    __syncthreads();
    float mu = mu_s, inv = inv_s;
    const float4* g4 = (const float4*)g;
    const float4* b4 = (const float4*)b;
    float4* o4 = (float4*)(out + row * (size_t)C_);
    {
        float4 gg = g4[tid], bb = b4[tid], r;
        r.x = tf32r((v0.x - mu) * inv * gg.x + bb.x);
        r.y = tf32r((v0.y - mu) * inv * gg.y + bb.y);
        r.z = tf32r((v0.z - mu) * inv * gg.z + bb.z);
        r.w = tf32r((v0.w - mu) * inv * gg.w + bb.w);
        o4[tid] = r;
    }
    {
        float4 gg = g4[tid + 256], bb = b4[tid + 256], r;
        r.x = tf32r((v1.x - mu) * inv * gg.x + bb.x);
        r.y = tf32r((v1.y - mu) * inv * gg.y + bb.y);
        r.z = tf32r((v1.z - mu) * inv * gg.z + bb.z);
        r.w = tf32r((v1.w - mu) * inv * gg.w + bb.w);
        o4[tid + 256] = r;
    }
}

// ---------------------------------------------------------------------------
// tf32 mma.sync GEMM: C[M,N] = A[M,K] @ BT[N,K]^T + bias (+gelu|+res|+qkv)
// CTA 128x128, K-tile 32, 8 warps 4(m)x2(n), warp tile 32x64, 3-stage pipe.
// 2 CTAs/SM (launch_bounds(256,2); 110.6KB smem each) -> 16 warps/SM.
// EPI_QKV: Q/K columns go to qkv buffer; V columns go transposed to vt.
// ---------------------------------------------------------------------------
#define EPI_NONE 0
#define EPI_GELU 1
#define EPI_RES  2
#define EPI_QKV  3

#define CTA_M 128
#define CTA_N 128
#define SSTRIDE 36
#define A_TILE_FLOATS (CTA_M * SSTRIDE)
#define B_TILE_FLOATS (CTA_N * SSTRIDE)
#define BUF_FLOATS    (A_TILE_FLOATS + B_TILE_FLOATS)  // 9216
#define N_STAGE 3
#define GEMM_SMEM     (N_STAGE * BUF_FLOATS * 4)       // 110592

__device__ __forceinline__ float fast_gelu(float v)
{
    float z = 0.79788456080286536f * (v + 0.044715f * v * v * v);
    float e = __expf(2.f * z);
    float th = 1.f - 2.f / (e + 1.f);
    return 0.5f * v * (1.f + th);
}

template<int EPI>
__global__ __launch_bounds__(256, 2) void mma_gemm(
    int M, int N, int K,
    const float* __restrict__ A, const float* __restrict__ BT,
    const float* __restrict__ bias, const float* __restrict__ R,
    float* __restrict__ C, float* __restrict__ VT)
{
    extern __shared__ float smf_g[];
    uint32_t sbase = smem_u32(smf_g);
    int tid  = threadIdx.x;
    int wid  = tid >> 5, lane = tid & 31;
    int gq   = lane >> 2, tq = lane & 3;
    int wm   = wid & 3, wn = wid >> 2;        // 4(m) x 2(n)
    int m0   = wm * 32, n0 = wn * 64;
    size_t rowBase = (size_t)blockIdx.y * CTA_M;
    size_t colBase = (size_t)blockIdx.x * CTA_N;

    const float* Ab = A  + rowBase * K;
    const float* Bb = BT + colBase * K;
    int fRow = tid >> 3;
    int fK   = (tid & 7) << 2;

    float acc[2][8][4];
    #pragma unroll
    for (int mf = 0; mf < 2; ++mf)
        #pragma unroll
        for (int nf = 0; nf < 8; ++nf)
            #pragma unroll
            for (int u = 0; u < 4; ++u) acc[mf][nf][u] = 0.f;

    int nk = K >> 5;

    auto fill = [&](int buf, int t) {
        uint32_t sa = sbase + (uint32_t)(buf * BUF_FLOATS * 4);
        uint32_t sb = sa + A_TILE_FLOATS * 4;
        #pragma unroll
        for (int it = 0; it < 4; ++it) {
            int row = fRow + it * 32;
            CP_ASYNC16(sa + (uint32_t)((row * SSTRIDE + fK) * 4),
                       Ab + (size_t)row * K + t * 32 + fK);
            CP_ASYNC16(sb + (uint32_t)((row * SSTRIDE + fK) * 4),
                       Bb + (size_t)row * K + t * 32 + fK);
        }
        CP_COMMIT();
    };

    fill(0, 0);
    fill(1, 1);
    int buf = 0;
    for (int t = 0; t < nk; ++t) {
        if (t + 2 < nk) { fill((buf + 2) % N_STAGE, t + 2); CP_WAIT(2); }
        else if (t + 1 < nk) { CP_WAIT(1); }
        else { CP_WAIT(0); }
        __syncthreads();

        const float* smA = smf_g + buf * BUF_FLOATS;
        const float* smB = smA + A_TILE_FLOATS;
        const uint32_t* aw = (const uint32_t*)smA + (m0 + gq) * SSTRIDE + tq;
        const uint32_t* bw = (const uint32_t*)smB + (n0 + gq) * SSTRIDE + tq;

        #pragma unroll
        for (int ks = 0; ks < 4; ++ks) {
            int k0 = ks * 8;
            uint32_t af[2][4];
            #pragma unroll
            for (int mf = 0; mf < 2; ++mf) {
                const uint32_t* p = aw + mf * 16 * SSTRIDE + k0;
                af[mf][0] = p[0];
                af[mf][1] = p[8 * SSTRIDE];
                af[mf][2] = p[4];
                af[mf][3] = p[8 * SSTRIDE + 4];
            }
            uint32_t bf[8][2];
            #pragma unroll
            for (int nf = 0; nf < 8; ++nf) {
                const uint32_t* p = bw + nf * 8 * SSTRIDE + k0;
                bf[nf][0] = p[0];
                bf[nf][1] = p[4];
            }
            #pragma unroll
            for (int mf = 0; mf < 2; ++mf)
                #pragma unroll
                for (int nf = 0; nf < 8; ++nf)
                    mma_tf32(acc[mf][nf], af[mf], bf[nf]);
        }
        __syncthreads();
        buf = (buf + 1) % N_STAGE;
    }

    bool vreg = (EPI == EPI_QKV) && (colBase >= 2 * C_);
    #pragma unroll
    for (int mf = 0; mf < 2; ++mf) {
        #pragma unroll
        for (int part = 0; part < 2; ++part) {
            size_t row = rowBase + m0 + mf * 16 + gq + part * 8;
            #pragma unroll
            for (int nf = 0; nf < 8; ++nf) {
                size_t col = colBase + n0 + nf * 8 + 2 * tq;
                float v0 = acc[mf][nf][part * 2 + 0];
                float v1 = acc[mf][nf][part * 2 + 1];
                float2 bb = *(const float2*)(bias + col);
                v0 += bb.x; v1 += bb.y;
                if (EPI == EPI_GELU) {
                    v0 = tf32r(fast_gelu(v0));
                    v1 = tf32r(fast_gelu(v1));
                }
                if (EPI == EPI_RES) {
                    float2 rv = *(const float2*)(R + row * N + col);
                    v0 += rv.x; v1 += rv.y;
                }
                if (vreg) {
                    size_t dall = col - 2 * C_;
                    size_t bh = (row >> 11) * NH_ + (dall >> 7);
                    size_t d  = dall & 127;
                    size_t tt = row & 2047;
                    VT[(bh * HD_ + d) * T_ + tt]       = tf32r(v0);
                    VT[(bh * HD_ + d + 1) * T_ + tt]   = tf32r(v1);
                } else {
                    *(float2*)(C + row * N + col) = make_float2(v0, v1);
                }
            }
        }
    }
}

// ---------------------------------------------------------------------------
// Tensor-core causal flash attention (tf32 mma). Grid: (32, 64). 128 threads.
// 4 warps; warp w owns q-rows 16w..16w+15. Tile: 64 q x 64 k, hd=128.
// ---------------------------------------------------------------------------
#define AQS 132
#define AVS 68
#define OFF_Q 0
#define OFF_K (64 * AQS)
#define OFF_V (2 * 64 * AQS)
#define OFF_P (2 * 64 * AQS + 128 * AVS)
#define ATTN_SMEM ((OFF_P + 64 * AVS) * 4)

__global__ __launch_bounds__(128) void attn_mma(const float* __restrict__ qkv,
                                                const float* __restrict__ vt,
                                                float* __restrict__ y)
{
    extern __shared__ float smf[];
    float* Qs = smf + OFF_Q;
    float* Ks = smf + OFF_K;
    float* Vs = smf + OFF_V;
    float* Ps = smf + OFF_P;

    int qt = blockIdx.x;
    int bh = blockIdx.y;
    int b  = bh >> 4;
    int h  = bh & 15;
    int tid = threadIdx.x;
    int wid = tid >> 5, lane = tid & 31;
    int gq  = lane >> 2, tq = lane & 3;
    const float scale = 0.08838834764831845f;

    const float* qbase = qkv + (size_t)b * T_ * C3_ + (size_t)h * HD_;
    const float* kbase = qbase + C_;
    const float* vbase = vt + (size_t)bh * HD_ * T_;
    int q0 = qt * 64;

    for (int i = tid; i < 64 * 32; i += 128) {
        int rr = i >> 5, c4 = (i & 31) << 2;
        float4 v = *(const float4*)(qbase + (size_t)(q0 + rr) * C3_ + c4);
        float* d = Qs + rr * AQS + c4;
        d[0] = tf32r(v.x * scale); d[1] = tf32r(v.y * scale);
        d[2] = tf32r(v.z * scale); d[3] = tf32r(v.w * scale);
    }

    float o[16][4];
    #pragma unroll
    for (int nd = 0; nd < 16; ++nd)
        #pragma unroll
        for (int u = 0; u < 4; ++u) o[nd][u] = 0.f;
    float m0 = -1e30f, m1 = -1e30f, l0 = 0.f, l1 = 0.f;

    int rowl0 = wid * 16 + gq;
    int rowl1 = rowl0 + 8;

    for (int kt = 0; kt <= qt; ++kt) {
        int k0 = kt * 64;
        __syncthreads();
        for (int i = tid; i < 64 * 32; i += 128) {
            int rr = i >> 5, c4 = (i & 31) << 2;
            float4 v = *(const float4*)(kbase + (size_t)(k0 + rr) * C3_ + c4);
            float* d = Ks + rr * AQS + c4;
            d[0] = tf32r(v.x); d[1] = tf32r(v.y);
            d[2] = tf32r(v.z); d[3] = tf32r(v.w);
        }
        for (int i = tid; i < 128 * 16; i += 128) {
            int dd = i >> 4, k4 = (i & 15) << 2;
            float4 v = *(const float4*)(vbase + (size_t)dd * T_ + k0 + k4);
            *(float4*)(Vs + dd * AVS + k4) = v;
        }
        __syncthreads();

        float s[8][4];
        #pragma unroll
        for (int nf = 0; nf < 8; ++nf)
            #pragma unroll
            for (int u = 0; u < 4; ++u) s[nf][u] = 0.f;

        const uint32_t* qw = (const uint32_t*)Qs + (wid * 16 + gq) * AQS + tq;
        const uint32_t* kw = (const uint32_t*)Ks + gq * AQS + tq;
        #pragma unroll
        for (int ks = 0; ks < 16; ++ks) {
            int kf = ks * 8;
            uint32_t af[4];
            af[0] = qw[kf];
            af[1] = qw[8 * AQS + kf];
            af[2] = qw[kf + 4];
            af[3] = qw[8 * AQS + kf + 4];
            #pragma unroll
            for (int nf = 0; nf < 8; ++nf) {
                const uint32_t* p = kw + nf * 8 * AQS + kf;
                uint32_t bf[2] = { p[0], p[4] };
                mma_tf32(s[nf], af, bf);
            }
        }

        if (kt == qt) {
            #pragma unroll
            for (int nf = 0; nf < 8; ++nf) {
                int col = nf * 8 + 2 * tq;
                if (col     > rowl0) s[nf][0] = -1e30f;
                if (col + 1 > rowl0) s[nf][1] = -1e30f;
                if (col     > rowl1) s[nf][2] = -1e30f;
                if (col + 1 > rowl1) s[nf][3] = -1e30f;
            }
        }

        float rmax0 = -1e30f, rmax1 = -1e30f;
        #pragma unroll
        for (int nf = 0; nf < 8; ++nf) {
            rmax0 = fmaxf(rmax0, fmaxf(s[nf][0], s[nf][1]));
            rmax1 = fmaxf(rmax1, fmaxf(s[nf][2], s[nf][3]));
        }
        rmax0 = fmaxf(rmax0, __shfl_xor_sync(0xffffffffu, rmax0, 1));
        rmax0 = fmaxf(rmax0, __shfl_xor_sync(0xffffffffu, rmax0, 2));
        rmax1 = fmaxf(rmax1, __shfl_xor_sync(0xffffffffu, rmax1, 1));
        rmax1 = fmaxf(rmax1, __shfl_xor_sync(0xffffffffu, rmax1, 2));

        float mn0 = fmaxf(m0, rmax0), mn1 = fmaxf(m1, rmax1);
        float c0 = __expf(m0 - mn0),  c1 = __expf(m1 - mn1);
        float sum0 = 0.f, sum1 = 0.f;
        #pragma unroll
        for (int nf = 0; nf < 8; ++nf) {
            s[nf][0] = __expf(s[nf][0] - mn0);
            s[nf][1] = __expf(s[nf][1] - mn0);
            s[nf][2] = __expf(s[nf][2] - mn1);
            s[nf][3] = __expf(s[nf][3] - mn1);
            sum0 += s[nf][0] + s[nf][1];
            sum1 += s[nf][2] + s[nf][3];
        }
        sum0 += __shfl_xor_sync(0xffffffffu, sum0, 1);
        sum0 += __shfl_xor_sync(0xffffffffu, sum0, 2);
        sum1 += __shfl_xor_sync(0xffffffffu, sum1, 1);
        sum1 += __shfl_xor_sync(0xffffffffu, sum1, 2);
        l0 = l0 * c0 + sum0;
        l1 = l1 * c1 + sum1;
        m0 = mn0; m1 = mn1;
        #pragma unroll
        for (int nd = 0; nd < 16; ++nd) {
            o[nd][0] *= c0; o[nd][1] *= c0;
            o[nd][2] *= c1; o[nd][3] *= c1;
        }

        {
            float* p0 = Ps + rowl0 * AVS + 2 * tq;
            float* p1 = Ps + rowl1 * AVS + 2 * tq;
            #pragma unroll
            for (int nf = 0; nf < 8; ++nf) {
                p0[nf * 8]     = tf32r(s[nf][0]);
                p0[nf * 8 + 1] = tf32r(s[nf][1]);
                p1[nf * 8]     = tf32r(s[nf][2]);
                p1[nf * 8 + 1] = tf32r(s[nf][3]);
            }
        }
        __syncwarp();

        const uint32_t* pw = (const uint32_t*)Ps + (wid * 16 + gq) * AVS + tq;
        const uint32_t* vw = (const uint32_t*)Vs + gq * AVS + tq;
        #pragma unroll
        for (int ks = 0; ks < 8; ++ks) {
            int kk = ks * 8;
            uint32_t af[4];
            af[0] = pw[kk];
            af[1] = pw[8 * AVS + kk];
            af[2] = pw[kk + 4];
            af[3] = pw[8 * AVS + kk + 4];
            #pragma unroll
            for (int nd = 0; nd < 16; ++nd) {
                const uint32_t* p = vw + nd * 8 * AVS + kk;
                uint32_t bf[2] = { p[0], p[4] };
                mma_tf32(o[nd], af, bf);
            }
        }
    }

    float inv0 = 1.f / l0, inv1 = 1.f / l1;
    size_t row0 = (size_t)(b * T_ + q0 + rowl0);
    size_t row1 = (size_t)(b * T_ + q0 + rowl1);
    #pragma unroll
    for (int nd = 0; nd < 16; ++nd) {
        size_t col = (size_t)h * HD_ + nd * 8 + 2 * tq;
        *(float2*)(y + row0 * C_ + col) =
            make_float2(tf32r(o[nd][0] * inv0), tf32r(o[nd][1] * inv0));
        *(float2*)(y + row1 * C_ + col) =
            make_float2(tf32r(o[nd][2] * inv1), tf32r(o[nd][3] * inv1));
    }
}

// ---------------------------------------------------------------------------
// Launch
// ---------------------------------------------------------------------------
extern "C" void kernel_launch(void* const* d_in, const int* in_sizes, int n_in,
                              void* d_out, int out_size)
{
    const float* x         = (const float*)d_in[0];
    const float* ln1_g     = (const float*)d_in[1];
    const float* ln1_b     = (const float*)d_in[2];
    const float* w_attn    = (const float*)d_in[3];
    const float* b_attn    = (const float*)d_in[4];
    const float* w_proj    = (const float*)d_in[5];
    const float* b_proj    = (const float*)d_in[6];
    const float* ln2_g     = (const float*)d_in[7];
    const float* ln2_b     = (const float*)d_in[8];
    const float* w_fc      = (const float*)d_in[9];
    const float* b_fc      = (const float*)d_in[10];
    const float* w_fc_proj = (const float*)d_in[11];
    const float* b_fc_proj = (const float*)d_in[12];
    float* out = (float*)d_out;

    float *h, *qkv, *vt, *y, *fc, *wt_attn, *wt_proj, *wt_fc, *wt_fcproj;
    cudaGetSymbolAddress((void**)&h,         g_h);
    cudaGetSymbolAddress((void**)&qkv,       g_qkv);
    cudaGetSymbolAddress((void**)&vt,        g_vt);
    cudaGetSymbolAddress((void**)&y,         g_y);
    cudaGetSymbolAddress((void**)&fc,        g_fc);
    cudaGetSymbolAddress((void**)&wt_attn,   g_wt_attn);
    cudaGetSymbolAddress((void**)&wt_proj,   g_wt_proj);
    cudaGetSymbolAddress((void**)&wt_fc,     g_wt_fc);
    cudaGetSymbolAddress((void**)&wt_fcproj, g_wt_fcproj);

    cudaFuncSetAttribute(attn_mma, cudaFuncAttributeMaxDynamicSharedMemorySize,
                         ATTN_SMEM);
    cudaFuncSetAttribute(mma_gemm<EPI_NONE>,
                         cudaFuncAttributeMaxDynamicSharedMemorySize, GEMM_SMEM);
    cudaFuncSetAttribute(mma_gemm<EPI_GELU>,
                         cudaFuncAttributeMaxDynamicSharedMemorySize, GEMM_SMEM);
    cudaFuncSetAttribute(mma_gemm<EPI_RES>,
                         cudaFuncAttributeMaxDynamicSharedMemorySize, GEMM_SMEM);
    cudaFuncSetAttribute(mma_gemm<EPI_QKV>,
                         cudaFuncAttributeMaxDynamicSharedMemorySize, GEMM_SMEM);

    dim3 tb(32, 8);

    // 1) w_attn^T ; h = LN1(x)
    transpose_k<<<dim3(C3_ / 32, C_ / 32), tb>>>(w_attn, wt_attn, C_, C3_);
    ln_k<<<BT_, 256>>>(x, ln1_g, ln1_b, h);
    // 2) qkv = h @ w_attn + b_attn   (V third written transposed to vt)
    mma_gemm<EPI_QKV><<<dim3(C3_ / CTA_N, BT_ / CTA_M), 256, GEMM_SMEM>>>(
        BT_, C3_, C_, h, wt_attn, b_attn, nullptr, qkv, vt);
    // 3) y = causal_attention(q, k, vt)
    attn_mma<<<dim3(T_ / 64, B_ * NH_), 128, ATTN_SMEM>>>(qkv, vt, y);
    // 4) w_proj^T ; out = x + y @ w_proj + b_proj
    transpose_k<<<dim3(C_ / 32, C_ / 32),  tb>>>(w_proj, wt_proj, C_, C_);
    mma_gemm<EPI_RES><<<dim3(C_ / CTA_N, BT_ / CTA_M), 256, GEMM_SMEM>>>(
        BT_, C_, C_, y, wt_proj, b_proj, x, out, nullptr);
    // 5) h = LN2(out)
    ln_k<<<BT_, 256>>>(out, ln2_g, ln2_b, h);
    // 6) w_fc^T ; fc = gelu(h @ w_fc + b_fc)
    transpose_k<<<dim3(C4_ / 32, C_ / 32), tb>>>(w_fc, wt_fc, C_, C4_);
    mma_gemm<EPI_GELU><<<dim3(C4_ / CTA_N, BT_ / CTA_M), 256, GEMM_SMEM>>>(
        BT_, C4_, C_, h, wt_fc, b_fc, nullptr, fc, nullptr);
    // 7) w_fc_proj^T ; out = out + fc @ w_fc_proj + b_fc_proj
    transpose_k<<<dim3(C_ / 32, C4_ / 32), tb>>>(w_fc_proj, wt_fcproj, C4_, C_);
    mma_gemm<EPI_RES><<<dim3(C_ / CTA_N, BT_ / CTA_M), 256, GEMM_SMEM>>>(
        BT_, C_, C4_, fc, wt_fcproj, b_fc_proj, out, out, nullptr);
}

// round 15
// speedup vs baseline: 1.1580x; 1.1580x over previous
#include <cuda_runtime.h>
#include <cstdint>
#include <cstddef>

// ---------------------------------------------------------------------------
// Problem dims (fixed): B=4, T=2048, C=2048, H=16, HD=128
// ---------------------------------------------------------------------------
#define B_  4
#define T_  2048
#define C_  2048
#define BT_ (B_ * T_)          // 8192
#define C3_ (3 * C_)           // 6144
#define C4_ (4 * C_)           // 8192
#define NH_ 16
#define HD_ 128

// ---------------------------------------------------------------------------
// Scratch (device globals: allocation-free rule)
// ---------------------------------------------------------------------------
__device__ float g_h[(size_t)BT_ * C_];       // LN output (tf32-rounded)
__device__ float g_qkv[(size_t)BT_ * C3_];    // Q,K (V third unused)
__device__ float g_vt[(size_t)BT_ * C_];      // V transposed: [b*h][d][t]
__device__ float g_y[(size_t)BT_ * C_];       // attention output (tf32-rounded)
__device__ float g_fc[(size_t)BT_ * C4_];     // gelu(fc) (tf32-rounded)
__device__ float g_wt_attn[(size_t)C3_ * C_];    // w_attn^T rounded
__device__ float g_wt_proj[(size_t)C_ * C_];     // w_proj^T rounded
__device__ float g_wt_fc[(size_t)C4_ * C_];      // w_fc^T rounded
__device__ float g_wt_fcproj[(size_t)C_ * C4_];  // w_fc_proj^T rounded

// ---------------------------------------------------------------------------
// Helpers
// ---------------------------------------------------------------------------
__device__ __forceinline__ uint32_t smem_u32(const void* p)
{
    return (uint32_t)__cvta_generic_to_shared(p);
}
#define CP_ASYNC16(dst, src) \
    asm volatile("cp.async.cg.shared.global [%0], [%1], 16;" \
                 :: "r"(dst), "l"(src) : "memory")
#define CP_COMMIT() asm volatile("cp.async.commit_group;" ::: "memory")
#define CP_WAIT(n)  asm volatile("cp.async.wait_group %0;" :: "n"(n) : "memory")

__device__ __forceinline__ float tf32r(float v)
{
    uint32_t u;
    asm("cvt.rna.tf32.f32 %0, %1;" : "=r"(u) : "f"(v));
    return __uint_as_float(u);
}

__device__ __forceinline__ void mma_tf32(float* c, const uint32_t* a,
                                         const uint32_t* b)
{
    asm volatile(
        "mma.sync.aligned.m16n8k8.row.col.f32.tf32.tf32.f32 "
        "{%0,%1,%2,%3}, {%4,%5,%6,%7}, {%8,%9}, {%0,%1,%2,%3};"
        : "+f"(c[0]), "+f"(c[1]), "+f"(c[2]), "+f"(c[3])
        : "r"(a[0]), "r"(a[1]), "r"(a[2]), "r"(a[3]), "r"(b[0]), "r"(b[1]));
}

// ---------------------------------------------------------------------------
// Weight transpose + tf32 rounding: in[R][Cc] -> out[Cc][R]
// ---------------------------------------------------------------------------
__global__ __launch_bounds__(256) void transpose_k(const float* __restrict__ in,
                                                   float* __restrict__ out,
                                                   int R, int Cc)
{
    __shared__ float t[32][33];
    int tx = threadIdx.x, ty = threadIdx.y;
    int bx = blockIdx.x * 32, by = blockIdx.y * 32;
    #pragma unroll
    for (int j = 0; j < 32; j += 8)
        t[ty + j][tx] = in[(size_t)(by + ty + j) * Cc + bx + tx];
    __syncthreads();
    #pragma unroll
    for (int j = 0; j < 32; j += 8)
        out[(size_t)(bx + ty + j) * R + by + tx] = tf32r(t[tx][ty + j]);
}

// ---------------------------------------------------------------------------
// LayerNorm: one block per row of 2048; output rounded to tf32 values
// ---------------------------------------------------------------------------
__global__ __launch_bounds__(256) void ln_k(const float* __restrict__ x,
                                            const float* __restrict__ g,
                                            const float* __restrict__ b,
                                            float* __restrict__ out)
{
    size_t row = blockIdx.x;
    const float4* xr = (const float4*)(x + row * (size_t)C_);
    int tid = threadIdx.x;
    float4 v0 = xr[tid];
    float4 v1 = xr[tid + 256];
    float s  = v0.x + v0.y + v0.z + v0.w + v1.x + v1.y + v1.z + v1.w;
    float s2 = v0.x*v0.x + v0.y*v0.y + v0.z*v0.z + v0.w*v0.w
             + v1.x*v1.x + v1.y*v1.y + v1.z*v1.z + v1.w*v1.w;
    #pragma unroll
    for (int o = 16; o > 0; o >>= 1) {
        s  += __shfl_xor_sync(0xffffffffu, s,  o);
        s2 += __shfl_xor_sync(0xffffffffu, s2, o);
    }
    __shared__ float ssum[8], ssq[8];
    __shared__ float mu_s, inv_s;
    int wid = tid >> 5, lane = tid & 31;
    if (lane == 0) { ssum[wid] = s; ssq[wid] = s2; }
    __syncthreads();
    if (tid == 0) {
        float S = 0.f, S2 = 0.f;
        #pragma unroll
        for (int i = 0; i < 8; ++i) { S += ssum[i]; S2 += ssq[i]; }
        float mu  = S * (1.f / (float)C_);
        float var = S2 * (1.f / (float)C_) - mu * mu;
        mu_s  = mu;
        inv_s = rsqrtf(var + 1e-5f);
    }
    __syncthreads();
    float mu = mu_s, inv = inv_s;
    const float4* g4 = (const float4*)g;
    const float4* b4 = (const float4*)b;
    float4* o4 = (float4*)(out + row * (size_t)C_);
    {
        float4 gg = g4[tid], bb = b4[tid], r;
        r.x = tf32r((v0.x - mu) * inv * gg.x + bb.x);
        r.y = tf32r((v0.y - mu) * inv * gg.y + bb.y);
        r.z = tf32r((v0.z - mu) * inv * gg.z + bb.z);
        r.w = tf32r((v0.w - mu) * inv * gg.w + bb.w);
        o4[tid] = r;
    }
    {
        float4 gg = g4[tid + 256], bb = b4[tid + 256], r;
        r.x = tf32r((v1.x - mu) * inv * gg.x + bb.x);
        r.y = tf32r((v1.y - mu) * inv * gg.y + bb.y);
        r.z = tf32r((v1.z - mu) * inv * gg.z + bb.z);
        r.w = tf32r((v1.w - mu) * inv * gg.w + bb.w);
        o4[tid + 256] = r;
    }
}

// ---------------------------------------------------------------------------
// tf32 mma.sync GEMM: C[M,N] = A[M,K] @ BT[N,K]^T + bias (+gelu|+res|+qkv)
// CTA 128x128, K-tile 32, 8 warps 4(m)x2(n), warp tile 32x64, 3-stage pipe.
// 2 CTAs/SM -> 16 warps/SM.
// ---------------------------------------------------------------------------
#define EPI_NONE 0
#define EPI_GELU 1
#define EPI_RES  2
#define EPI_QKV  3

#define CTA_M 128
#define CTA_N 128
#define SSTRIDE 36
#define A_TILE_FLOATS (CTA_M * SSTRIDE)
#define B_TILE_FLOATS (CTA_N * SSTRIDE)
#define BUF_FLOATS    (A_TILE_FLOATS + B_TILE_FLOATS)  // 9216
#define N_STAGE 3
#define GEMM_SMEM     (N_STAGE * BUF_FLOATS * 4)       // 110592

__device__ __forceinline__ float fast_gelu(float v)
{
    float z = 0.79788456080286536f * (v + 0.044715f * v * v * v);
    float e = __expf(2.f * z);
    float th = 1.f - 2.f / (e + 1.f);
    return 0.5f * v * (1.f + th);
}

template<int EPI>
__global__ __launch_bounds__(256, 2) void mma_gemm(
    int M, int N, int K,
    const float* __restrict__ A, const float* __restrict__ BT,
    const float* __restrict__ bias, const float* __restrict__ R,
    float* __restrict__ C, float* __restrict__ VT)
{
    extern __shared__ float smf_g[];
    uint32_t sbase = smem_u32(smf_g);
    int tid  = threadIdx.x;
    int wid  = tid >> 5, lane = tid & 31;
    int gq   = lane >> 2, tq = lane & 3;
    int wm   = wid & 3, wn = wid >> 2;        // 4(m) x 2(n)
    int m0   = wm * 32, n0 = wn * 64;
    size_t rowBase = (size_t)blockIdx.y * CTA_M;
    size_t colBase = (size_t)blockIdx.x * CTA_N;

    const float* Ab = A  + rowBase * K;
    const float* Bb = BT + colBase * K;
    int fRow = tid >> 3;
    int fK   = (tid & 7) << 2;

    float acc[2][8][4];
    #pragma unroll
    for (int mf = 0; mf < 2; ++mf)
        #pragma unroll
        for (int nf = 0; nf < 8; ++nf)
            #pragma unroll
            for (int u = 0; u < 4; ++u) acc[mf][nf][u] = 0.f;

    int nk = K >> 5;

    auto fill = [&](int buf, int t) {
        uint32_t sa = sbase + (uint32_t)(buf * BUF_FLOATS * 4);
        uint32_t sb = sa + A_TILE_FLOATS * 4;
        #pragma unroll
        for (int it = 0; it < 4; ++it) {
            int row = fRow + it * 32;
            CP_ASYNC16(sa + (uint32_t)((row * SSTRIDE + fK) * 4),
                       Ab + (size_t)row * K + t * 32 + fK);
            CP_ASYNC16(sb + (uint32_t)((row * SSTRIDE + fK) * 4),
                       Bb + (size_t)row * K + t * 32 + fK);
        }
        CP_COMMIT();
    };

    fill(0, 0);
    fill(1, 1);
    int buf = 0;
    for (int t = 0; t < nk; ++t) {
        if (t + 2 < nk) { fill((buf + 2) % N_STAGE, t + 2); CP_WAIT(2); }
        else if (t + 1 < nk) { CP_WAIT(1); }
        else { CP_WAIT(0); }
        __syncthreads();

        const float* smA = smf_g + buf * BUF_FLOATS;
        const float* smB = smA + A_TILE_FLOATS;
        const uint32_t* aw = (const uint32_t*)smA + (m0 + gq) * SSTRIDE + tq;
        const uint32_t* bw = (const uint32_t*)smB + (n0 + gq) * SSTRIDE + tq;

        #pragma unroll
        for (int ks = 0; ks < 4; ++ks) {
            int k0 = ks * 8;
            uint32_t af[2][4];
            #pragma unroll
            for (int mf = 0; mf < 2; ++mf) {
                const uint32_t* p = aw + mf * 16 * SSTRIDE + k0;
                af[mf][0] = p[0];
                af[mf][1] = p[8 * SSTRIDE];
                af[mf][2] = p[4];
                af[mf][3] = p[8 * SSTRIDE + 4];
            }
            uint32_t bf[8][2];
            #pragma unroll
            for (int nf = 0; nf < 8; ++nf) {
                const uint32_t* p = bw + nf * 8 * SSTRIDE + k0;
                bf[nf][0] = p[0];
                bf[nf][1] = p[4];
            }
            #pragma unroll
            for (int mf = 0; mf < 2; ++mf)
                #pragma unroll
                for (int nf = 0; nf < 8; ++nf)
                    mma_tf32(acc[mf][nf], af[mf], bf[nf]);
        }
        __syncthreads();
        buf = (buf + 1) % N_STAGE;
    }

    bool vreg = (EPI == EPI_QKV) && (colBase >= 2 * C_);
    #pragma unroll
    for (int mf = 0; mf < 2; ++mf) {
        #pragma unroll
        for (int part = 0; part < 2; ++part) {
            size_t row = rowBase + m0 + mf * 16 + gq + part * 8;
            #pragma unroll
            for (int nf = 0; nf < 8; ++nf) {
                size_t col = colBase + n0 + nf * 8 + 2 * tq;
                float v0 = acc[mf][nf][part * 2 + 0];
                float v1 = acc[mf][nf][part * 2 + 1];
                float2 bb = *(const float2*)(bias + col);
                v0 += bb.x; v1 += bb.y;
                if (EPI == EPI_GELU) {
                    v0 = tf32r(fast_gelu(v0));
                    v1 = tf32r(fast_gelu(v1));
                }
                if (EPI == EPI_RES) {
                    float2 rv = *(const float2*)(R + row * N + col);
                    v0 += rv.x; v1 += rv.y;
                }
                if (vreg) {
                    size_t dall = col - 2 * C_;
                    size_t bh = (row >> 11) * NH_ + (dall >> 7);
                    size_t d  = dall & 127;
                    size_t tt = row & 2047;
                    VT[(bh * HD_ + d) * T_ + tt]       = tf32r(v0);
                    VT[(bh * HD_ + d + 1) * T_ + tt]   = tf32r(v1);
                } else {
                    *(float2*)(C + row * N + col) = make_float2(v0, v1);
                }
            }
        }
    }
}

// ---------------------------------------------------------------------------
// Tensor-core causal flash attention (tf32 mma). Grid: (16, 64). 256 threads.
// 8 warps; warp w owns q-rows 16w..16w+15 of a 128-row q-tile. K-tile 64.
// Q/K staged stride 132, V [d][68], P [row][68]; all fragment LDS
// conflict-free (stride ≡ 4 mod 32).
// ---------------------------------------------------------------------------
#define QT_ROWS 128
#define AQS 132
#define AVS 68
#define OFF_Q 0
#define OFF_K (QT_ROWS * AQS)                   // 16896
#define OFF_V (OFF_K + 64 * AQS)                // 25344
#define OFF_P (OFF_V + 128 * AVS)               // 34048
#define ATTN_SMEM ((OFF_P + QT_ROWS * AVS) * 4) // 171008 bytes

__global__ __launch_bounds__(256) void attn_mma(const float* __restrict__ qkv,
                                                const float* __restrict__ vt,
                                                float* __restrict__ y)
{
    extern __shared__ float smf[];
    float* Qs = smf + OFF_Q;
    float* Ks = smf + OFF_K;
    float* Vs = smf + OFF_V;
    float* Ps = smf + OFF_P;

    int qt = blockIdx.x;
    int bh = blockIdx.y;
    int b  = bh >> 4;
    int h  = bh & 15;
    int tid = threadIdx.x;
    int wid = tid >> 5, lane = tid & 31;
    int gq  = lane >> 2, tq = lane & 3;
    const float scale = 0.08838834764831845f;

    const float* qbase = qkv + (size_t)b * T_ * C3_ + (size_t)h * HD_;
    const float* kbase = qbase + C_;
    const float* vbase = vt + (size_t)bh * HD_ * T_;
    int q0 = qt * QT_ROWS;

    // stage Q (scaled + tf32-rounded): 128 rows x 128 d
    for (int i = tid; i < QT_ROWS * 32; i += 256) {
        int rr = i >> 5, c4 = (i & 31) << 2;
        float4 v = *(const float4*)(qbase + (size_t)(q0 + rr) * C3_ + c4);
        float* d = Qs + rr * AQS + c4;
        d[0] = tf32r(v.x * scale); d[1] = tf32r(v.y * scale);
        d[2] = tf32r(v.z * scale); d[3] = tf32r(v.w * scale);
    }

    float o[16][4];
    #pragma unroll
    for (int nd = 0; nd < 16; ++nd)
        #pragma unroll
        for (int u = 0; u < 4; ++u) o[nd][u] = 0.f;
    float m0 = -1e30f, m1 = -1e30f, l0 = 0.f, l1 = 0.f;

    int rowl0 = wid * 16 + gq;       // local q row (0..127)
    int rowl1 = rowl0 + 8;
    int nkt = 2 * qt + 2;            // k-tiles of 64 covering <= q0+127

    for (int kt = 0; kt < nkt; ++kt) {
        int k0 = kt * 64;
        __syncthreads();   // prior-tile readers done (covers Q load on iter 0)
        // stage K (tf32-rounded): 64 rows
        for (int i = tid; i < 64 * 32; i += 256) {
            int rr = i >> 5, c4 = (i & 31) << 2;
            float4 v = *(const float4*)(kbase + (size_t)(k0 + rr) * C3_ + c4);
            float* d = Ks + rr * AQS + c4;
            d[0] = tf32r(v.x); d[1] = tf32r(v.y);
            d[2] = tf32r(v.z); d[3] = tf32r(v.w);
        }
        // stage V^T slice: Vs[d][key] (tf32 values already)
        for (int i = tid; i < 128 * 16; i += 256) {
            int dd = i >> 4, k4 = (i & 15) << 2;
            float4 v = *(const float4*)(vbase + (size_t)dd * T_ + k0 + k4);
            *(float4*)(Vs + dd * AVS + k4) = v;
        }
        __syncthreads();

        // ---- S = Q.K^T  (warp: 16 rows x 64 keys) ----
        float s[8][4];
        #pragma unroll
        for (int nf = 0; nf < 8; ++nf)
            #pragma unroll
            for (int u = 0; u < 4; ++u) s[nf][u] = 0.f;

        const uint32_t* qw = (const uint32_t*)Qs + (wid * 16 + gq) * AQS + tq;
        const uint32_t* kw = (const uint32_t*)Ks + gq * AQS + tq;
        #pragma unroll
        for (int ks = 0; ks < 16; ++ks) {
            int kf = ks * 8;
            uint32_t af[4];
            af[0] = qw[kf];
            af[1] = qw[8 * AQS + kf];
            af[2] = qw[kf + 4];
            af[3] = qw[8 * AQS + kf + 4];
            #pragma unroll
            for (int nf = 0; nf < 8; ++nf) {
                const uint32_t* p = kw + nf * 8 * AQS + kf;
                uint32_t bf[2] = { p[0], p[4] };
                mma_tf32(s[nf], af, bf);
            }
        }

        // ---- causal mask (diagonal band only) ----
        if (k0 + 63 > rowl0) {       // local coords: k0 local == global - q0*?  no:
            // global col = k0 + colf, global row = q0 + rowl; mask col > row
            #pragma unroll
            for (int nf = 0; nf < 8; ++nf) {
                int colf = k0 + nf * 8 + 2 * tq;
                if (colf     > q0 + rowl0) s[nf][0] = -1e30f;
                if (colf + 1 > q0 + rowl0) s[nf][1] = -1e30f;
                if (colf     > q0 + rowl1) s[nf][2] = -1e30f;
                if (colf + 1 > q0 + rowl1) s[nf][3] = -1e30f;
            }
        }

        // ---- online softmax on fragments ----
        float rmax0 = -1e30f, rmax1 = -1e30f;
        #pragma unroll
        for (int nf = 0; nf < 8; ++nf) {
            rmax0 = fmaxf(rmax0, fmaxf(s[nf][0], s[nf][1]));
            rmax1 = fmaxf(rmax1, fmaxf(s[nf][2], s[nf][3]));
        }
        rmax0 = fmaxf(rmax0, __shfl_xor_sync(0xffffffffu, rmax0, 1));
        rmax0 = fmaxf(rmax0, __shfl_xor_sync(0xffffffffu, rmax0, 2));
        rmax1 = fmaxf(rmax1, __shfl_xor_sync(0xffffffffu, rmax1, 1));
        rmax1 = fmaxf(rmax1, __shfl_xor_sync(0xffffffffu, rmax1, 2));

        float mn0 = fmaxf(m0, rmax0), mn1 = fmaxf(m1, rmax1);
        float c0 = __expf(m0 - mn0),  c1 = __expf(m1 - mn1);
        float sum0 = 0.f, sum1 = 0.f;
        #pragma unroll
        for (int nf = 0; nf < 8; ++nf) {
            s[nf][0] = __expf(s[nf][0] - mn0);
            s[nf][1] = __expf(s[nf][1] - mn0);
            s[nf][2] = __expf(s[nf][2] - mn1);
            s[nf][3] = __expf(s[nf][3] - mn1);
            sum0 += s[nf][0] + s[nf][1];
            sum1 += s[nf][2] + s[nf][3];
        }
        sum0 += __shfl_xor_sync(0xffffffffu, sum0, 1);
        sum0 += __shfl_xor_sync(0xffffffffu, sum0, 2);
        sum1 += __shfl_xor_sync(0xffffffffu, sum1, 1);
        sum1 += __shfl_xor_sync(0xffffffffu, sum1, 2);
        l0 = l0 * c0 + sum0;
        l1 = l1 * c1 + sum1;
        m0 = mn0; m1 = mn1;
        #pragma unroll
        for (int nd = 0; nd < 16; ++nd) {
            o[nd][0] *= c0; o[nd][1] *= c0;
            o[nd][2] *= c1; o[nd][3] *= c1;
        }

        // ---- write P to smem (warp-private rows), reload as A fragments ----
        {
            float* p0 = Ps + rowl0 * AVS + 2 * tq;
            float* p1 = Ps + rowl1 * AVS + 2 * tq;
            #pragma unroll
            for (int nf = 0; nf < 8; ++nf) {
                p0[nf * 8]     = tf32r(s[nf][0]);
                p0[nf * 8 + 1] = tf32r(s[nf][1]);
                p1[nf * 8]     = tf32r(s[nf][2]);
                p1[nf * 8 + 1] = tf32r(s[nf][3]);
            }
        }
        __syncwarp();

        // ---- O += P.V ----
        const uint32_t* pw = (const uint32_t*)Ps + (wid * 16 + gq) * AVS + tq;
        const uint32_t* vw = (const uint32_t*)Vs + gq * AVS + tq;
        #pragma unroll
        for (int ks = 0; ks < 8; ++ks) {
            int kk = ks * 8;
            uint32_t af[4];
            af[0] = pw[kk];
            af[1] = pw[8 * AVS + kk];
            af[2] = pw[kk + 4];
            af[3] = pw[8 * AVS + kk + 4];
            #pragma unroll
            for (int nd = 0; nd < 16; ++nd) {
                const uint32_t* p = vw + nd * 8 * AVS + kk;
                uint32_t bf[2] = { p[0], p[4] };
                mma_tf32(o[nd], af, bf);
            }
        }
    }

    // ---- normalize + store (tf32-rounded; feeds proj GEMM) ----
    float inv0 = 1.f / l0, inv1 = 1.f / l1;
    size_t row0 = (size_t)(b * T_ + q0 + rowl0);
    size_t row1 = (size_t)(b * T_ + q0 + rowl1);
    #pragma unroll
    for (int nd = 0; nd < 16; ++nd) {
        size_t col = (size_t)h * HD_ + nd * 8 + 2 * tq;
        *(float2*)(y + row0 * C_ + col) =
            make_float2(tf32r(o[nd][0] * inv0), tf32r(o[nd][1] * inv0));
        *(float2*)(y + row1 * C_ + col) =
            make_float2(tf32r(o[nd][2] * inv1), tf32r(o[nd][3] * inv1));
    }
}

// ---------------------------------------------------------------------------
// Launch
// ---------------------------------------------------------------------------
extern "C" void kernel_launch(void* const* d_in, const int* in_sizes, int n_in,
                              void* d_out, int out_size)
{
    const float* x         = (const float*)d_in[0];
    const float* ln1_g     = (const float*)d_in[1];
    const float* ln1_b     = (const float*)d_in[2];
    const float* w_attn    = (const float*)d_in[3];
    const float* b_attn    = (const float*)d_in[4];
    const float* w_proj    = (const float*)d_in[5];
    const float* b_proj    = (const float*)d_in[6];
    const float* ln2_g     = (const float*)d_in[7];
    const float* ln2_b     = (const float*)d_in[8];
    const float* w_fc      = (const float*)d_in[9];
    const float* b_fc      = (const float*)d_in[10];
    const float* w_fc_proj = (const float*)d_in[11];
    const float* b_fc_proj = (const float*)d_in[12];
    float* out = (float*)d_out;

    float *h, *qkv, *vt, *y, *fc, *wt_attn, *wt_proj, *wt_fc, *wt_fcproj;
    cudaGetSymbolAddress((void**)&h,         g_h);
    cudaGetSymbolAddress((void**)&qkv,       g_qkv);
    cudaGetSymbolAddress((void**)&vt,        g_vt);
    cudaGetSymbolAddress((void**)&y,         g_y);
    cudaGetSymbolAddress((void**)&fc,        g_fc);
    cudaGetSymbolAddress((void**)&wt_attn,   g_wt_attn);
    cudaGetSymbolAddress((void**)&wt_proj,   g_wt_proj);
    cudaGetSymbolAddress((void**)&wt_fc,     g_wt_fc);
    cudaGetSymbolAddress((void**)&wt_fcproj, g_wt_fcproj);

    cudaFuncSetAttribute(attn_mma, cudaFuncAttributeMaxDynamicSharedMemorySize,
                         ATTN_SMEM);
    cudaFuncSetAttribute(mma_gemm<EPI_NONE>,
                         cudaFuncAttributeMaxDynamicSharedMemorySize, GEMM_SMEM);
    cudaFuncSetAttribute(mma_gemm<EPI_GELU>,
                         cudaFuncAttributeMaxDynamicSharedMemorySize, GEMM_SMEM);
    cudaFuncSetAttribute(mma_gemm<EPI_RES>,
                         cudaFuncAttributeMaxDynamicSharedMemorySize, GEMM_SMEM);
    cudaFuncSetAttribute(mma_gemm<EPI_QKV>,
                         cudaFuncAttributeMaxDynamicSharedMemorySize, GEMM_SMEM);

    dim3 tb(32, 8);

    // 1) w_attn^T ; h = LN1(x)
    transpose_k<<<dim3(C3_ / 32, C_ / 32), tb>>>(w_attn, wt_attn, C_, C3_);
    ln_k<<<BT_, 256>>>(x, ln1_g, ln1_b, h);
    // 2) qkv = h @ w_attn + b_attn   (V third written transposed to vt)
    mma_gemm<EPI_QKV><<<dim3(C3_ / CTA_N, BT_ / CTA_M), 256, GEMM_SMEM>>>(
        BT_, C3_, C_, h, wt_attn, b_attn, nullptr, qkv, vt);
    // 3) y = causal_attention(q, k, vt)
    attn_mma<<<dim3(T_ / QT_ROWS, B_ * NH_), 256, ATTN_SMEM>>>(qkv, vt, y);
    // 4) w_proj^T ; out = x + y @ w_proj + b_proj
    transpose_k<<<dim3(C_ / 32, C_ / 32),  tb>>>(w_proj, wt_proj, C_, C_);
    mma_gemm<EPI_RES><<<dim3(C_ / CTA_N, BT_ / CTA_M), 256, GEMM_SMEM>>>(
        BT_, C_, C_, y, wt_proj, b_proj, x, out, nullptr);
    // 5) h = LN2(out)
    ln_k<<<BT_, 256>>>(out, ln2_g, ln2_b, h);
    // 6) w_fc^T ; fc = gelu(h @ w_fc + b_fc)
    transpose_k<<<dim3(C4_ / 32, C_ / 32), tb>>>(w_fc, wt_fc, C_, C4_);
    mma_gemm<EPI_GELU><<<dim3(C4_ / CTA_N, BT_ / CTA_M), 256, GEMM_SMEM>>>(
        BT_, C4_, C_, h, wt_fc, b_fc, nullptr, fc, nullptr);
    // 7) w_fc_proj^T ; out = out + fc @ w_fc_proj + b_fc_proj
    transpose_k<<<dim3(C_ / 32, C4_ / 32), tb>>>(w_fc_proj, wt_fcproj, C4_, C_);
    mma_gemm<EPI_RES><<<dim3(C_ / CTA_N, BT_ / CTA_M), 256, GEMM_SMEM>>>(
        BT_, C_, C4_, fc, wt_fcproj, b_fc_proj, out, out, nullptr);
}